// round 5
// baseline (speedup 1.0000x reference)
#include <cuda_runtime.h>
#include <cstdint>

// Problem shape (fixed for this dataset entry)
#define B_    2
#define N_    50000
#define C_    64
#define M_    50000
#define K_    16
#define H_    8
#define CMID_ 16

// Runtime-detected index width flag (int64 vs int32), set by detect kernel.
__device__ int g_idx_is64;

__global__ void detect_idx_kernel(const unsigned int* __restrict__ w) {
    if (threadIdx.x == 0 && blockIdx.x == 0) {
        int is64 = 1;
        #pragma unroll 1
        for (int i = 0; i < 256; i++) {
            if (w[2 * i + 1] != 0u) { is64 = 0; break; }
        }
        g_idx_is64 = is64;
    }
}

// One WARP per point; 4 points per 128-thread CTA. No staging smem except idx.
// Lane l: cg = l&7 owns 8 contiguous channels [8cg,8cg+8) == ONE guidance
// head; jq = l>>3 owns w quad [4jq,4jq+4).
// Accumulators pair along CHANNELS: acc[cp][j] = {out[2cp][wj], out[2cp+1][wj]}
// so the multiplier {f,f'}*{g,g} comes pre-packed from the gather LDG.128
// (one mul.rn.f32x2), and only the 4 W scalars need dup movs.
// Per k (lane): 2 LDG.128 gather + 1 LDG.128 W + 1 scalar LDG guid
//               + 1 dup + 4 mul.f32x2 + 4 dup + 16 fma.f32x2.
__global__ void __launch_bounds__(128, 6)
pcf_kernel(const float* __restrict__ feat,
           const void*  __restrict__ inds_raw,
           const float* __restrict__ guid,
           const float* __restrict__ wn,
           float* __restrict__ out)
{
    __shared__ int sidx[4][K_];

    const int wid  = threadIdx.x >> 5;
    const int lane = threadIdx.x & 31;
    const int p    = blockIdx.x * 4 + wid;      // point id in [0, B*M)
    const int b    = (p >= M_) ? 1 : 0;
    const int cg   = lane & 7;                  // channel group (== head)
    const int jq   = lane >> 3;                 // w quad 0..3

    if (lane < K_) {
        long long idx;
        if (g_idx_is64) idx = ((const long long*)inds_raw)[(size_t)p * K_ + lane];
        else            idx = (long long)((const int*)inds_raw)[(size_t)p * K_ + lane];
        sidx[wid][lane] = (int)idx;
    }
    __syncwarp();

    const float* fb   = feat + (size_t)b * ((size_t)N_ * C_) + 8 * cg;
    const float* wrow = wn   + (size_t)p * (K_ * CMID_) + 4 * jq;
    const float* grow = guid + (size_t)p * (K_ * H_) + cg;

    unsigned long long acc[16];
    #pragma unroll
    for (int i = 0; i < 16; i++) acc[i] = 0ull;

    #pragma unroll 4
    for (int k = 0; k < K_; k++) {
        const int ix = sidx[wid][k];
        const ulonglong2* fr = (const ulonglong2*)(fb + (size_t)ix * C_);
        ulonglong2 A0 = fr[0];   // packed {f0,f1},{f2,f3} of this lane's 8 ch
        ulonglong2 A1 = fr[1];   // packed {f4,f5},{f6,f7}

        const float g = __ldg(grow + k * H_);    // single head per lane
        unsigned long long gg;
        asm("mov.b64 %0, {%1, %1};" : "=l"(gg) : "f"(g));

        unsigned long long s0, s1, s2, s3;       // scaled channel-pairs
        asm("mul.rn.f32x2 %0, %1, %2;" : "=l"(s0) : "l"(A0.x), "l"(gg));
        asm("mul.rn.f32x2 %0, %1, %2;" : "=l"(s1) : "l"(A0.y), "l"(gg));
        asm("mul.rn.f32x2 %0, %1, %2;" : "=l"(s2) : "l"(A1.x), "l"(gg));
        asm("mul.rn.f32x2 %0, %1, %2;" : "=l"(s3) : "l"(A1.y), "l"(gg));

        const float4 W = __ldg((const float4*)(wrow + k * CMID_));  // 4 w vals
        unsigned long long w0, w1, w2, w3;
        asm("mov.b64 %0, {%1, %1};" : "=l"(w0) : "f"(W.x));
        asm("mov.b64 %0, {%1, %1};" : "=l"(w1) : "f"(W.y));
        asm("mov.b64 %0, {%1, %1};" : "=l"(w2) : "f"(W.z));
        asm("mov.b64 %0, {%1, %1};" : "=l"(w3) : "f"(W.w));

        asm("fma.rn.f32x2 %0, %1, %2, %3;" : "=l"(acc[ 0]) : "l"(s0), "l"(w0), "l"(acc[ 0]));
        asm("fma.rn.f32x2 %0, %1, %2, %3;" : "=l"(acc[ 1]) : "l"(s0), "l"(w1), "l"(acc[ 1]));
        asm("fma.rn.f32x2 %0, %1, %2, %3;" : "=l"(acc[ 2]) : "l"(s0), "l"(w2), "l"(acc[ 2]));
        asm("fma.rn.f32x2 %0, %1, %2, %3;" : "=l"(acc[ 3]) : "l"(s0), "l"(w3), "l"(acc[ 3]));
        asm("fma.rn.f32x2 %0, %1, %2, %3;" : "=l"(acc[ 4]) : "l"(s1), "l"(w0), "l"(acc[ 4]));
        asm("fma.rn.f32x2 %0, %1, %2, %3;" : "=l"(acc[ 5]) : "l"(s1), "l"(w1), "l"(acc[ 5]));
        asm("fma.rn.f32x2 %0, %1, %2, %3;" : "=l"(acc[ 6]) : "l"(s1), "l"(w2), "l"(acc[ 6]));
        asm("fma.rn.f32x2 %0, %1, %2, %3;" : "=l"(acc[ 7]) : "l"(s1), "l"(w3), "l"(acc[ 7]));
        asm("fma.rn.f32x2 %0, %1, %2, %3;" : "=l"(acc[ 8]) : "l"(s2), "l"(w0), "l"(acc[ 8]));
        asm("fma.rn.f32x2 %0, %1, %2, %3;" : "=l"(acc[ 9]) : "l"(s2), "l"(w1), "l"(acc[ 9]));
        asm("fma.rn.f32x2 %0, %1, %2, %3;" : "=l"(acc[10]) : "l"(s2), "l"(w2), "l"(acc[10]));
        asm("fma.rn.f32x2 %0, %1, %2, %3;" : "=l"(acc[11]) : "l"(s2), "l"(w3), "l"(acc[11]));
        asm("fma.rn.f32x2 %0, %1, %2, %3;" : "=l"(acc[12]) : "l"(s3), "l"(w0), "l"(acc[12]));
        asm("fma.rn.f32x2 %0, %1, %2, %3;" : "=l"(acc[13]) : "l"(s3), "l"(w1), "l"(acc[13]));
        asm("fma.rn.f32x2 %0, %1, %2, %3;" : "=l"(acc[14]) : "l"(s3), "l"(w2), "l"(acc[14]));
        asm("fma.rn.f32x2 %0, %1, %2, %3;" : "=l"(acc[15]) : "l"(s3), "l"(w3), "l"(acc[15]));
    }

    // ---- epilogue: row 2cp gets lo halves of acc[cp][0..3], row 2cp+1 the hi
    float* o = out + (size_t)p * (C_ * CMID_) + (size_t)(8 * cg) * CMID_ + 4 * jq;
    #pragma unroll
    for (int cp = 0; cp < 4; cp++) {
        float2 v0 = *(float2*)&acc[cp * 4 + 0];
        float2 v1 = *(float2*)&acc[cp * 4 + 1];
        float2 v2 = *(float2*)&acc[cp * 4 + 2];
        float2 v3 = *(float2*)&acc[cp * 4 + 3];
        *(float4*)(o + (2 * cp) * CMID_)     = make_float4(v0.x, v1.x, v2.x, v3.x);
        *(float4*)(o + (2 * cp + 1) * CMID_) = make_float4(v0.y, v1.y, v2.y, v3.y);
    }
}

extern "C" void kernel_launch(void* const* d_in, const int* in_sizes, int n_in,
                              void* d_out, int out_size) {
    const float* feat = (const float*)d_in[0];
    const void*  inds = d_in[1];
    const float* guid = (const float*)d_in[2];
    const float* wn   = (const float*)d_in[3];
    float* out = (float*)d_out;

    detect_idx_kernel<<<1, 32>>>((const unsigned int*)inds);
    pcf_kernel<<<(B_ * M_) / 4, 128>>>(feat, inds, guid, wn, out);
}

// round 6
// speedup vs baseline: 1.2507x; 1.2507x over previous
#include <cuda_runtime.h>
#include <cstdint>

// Problem shape (fixed for this dataset entry)
#define B_    2
#define N_    50000
#define C_    64
#define M_    50000
#define K_    16
#define H_    8
#define CMID_ 16

// Runtime-detected index width flag (int64 vs int32), set by detect kernel.
__device__ int g_idx_is64;

__global__ void detect_idx_kernel(const unsigned int* __restrict__ w) {
    if (threadIdx.x == 0 && blockIdx.x == 0) {
        int is64 = 1;
        #pragma unroll 1
        for (int i = 0; i < 256; i++) {
            if (w[2 * i + 1] != 0u) { is64 = 0; break; }
        }
        g_idx_is64 = is64;
    }
}

// One WARP per point; 4 points per 128-thread CTA.
// Lane l: cq = l&15 owns 4 contiguous channels [4cq,4cq+4) (single guidance
// head, since 4 | 8); wh = l>>4 owns w half [8wh, 8wh+8).
// Gather: ONE LDG.128 per k (16 lanes cover the 256B row; 2-dup, 2 lines).
// W: smem, 2 lane-uniform LDS.128 per k (vs 4 in R3 -- the dominant L1 term).
// Accums pack along channels: acc[i][j] = {out[4cq+2i][w], out[4cq+2i+1][w]},
// multiplier comes packed from the gather load via mul.rn.f32x2; only the 8 W
// scalars need dup movs. 16 fma.rn.f32x2 per k unchanged.
__global__ void __launch_bounds__(128, 7)
pcf_kernel(const float* __restrict__ feat,
           const void*  __restrict__ inds_raw,
           const float* __restrict__ guid,
           const float* __restrict__ wn,
           float* __restrict__ out)
{
    __shared__ __align__(16) float swn[4][K_ * CMID_];  // 4 x 1KB  weightnet
    __shared__ __align__(16) float sgd[4][K_ * H_];     // 4 x 512B guidance
    __shared__ int sidx[4][K_];

    const int wid  = threadIdx.x >> 5;
    const int lane = threadIdx.x & 31;
    const int p    = blockIdx.x * 4 + wid;      // point id in [0, B*M)
    const int b    = (p >= M_) ? 1 : 0;
    const int cq   = lane & 15;                 // channel quad 0..15
    const int wh   = lane >> 4;                 // w half 0..1
    const int hd   = cq >> 1;                   // guidance head of channels 4cq..

    // ---- per-warp staging: weightnet (1KB), guidance (512B), indices ----
    {
        const float4* wsrc = (const float4*)(wn + (size_t)p * (K_ * CMID_));
        float4* wdst = (float4*)(swn[wid]);
        wdst[lane]      = wsrc[lane];
        wdst[lane + 32] = wsrc[lane + 32];
        ((float4*)(sgd[wid]))[lane] = ((const float4*)(guid + (size_t)p * (K_ * H_)))[lane];
        if (lane < K_) {
            long long idx;
            if (g_idx_is64) idx = ((const long long*)inds_raw)[(size_t)p * K_ + lane];
            else            idx = (long long)((const int*)inds_raw)[(size_t)p * K_ + lane];
            sidx[wid][lane] = (int)idx;
        }
    }
    __syncwarp();

    // lane-fixed channel base: this lane's 4 channels start at 4*cq
    const float* fb = feat + (size_t)b * ((size_t)N_ * C_) + 4 * cq;

    unsigned long long acc[16];
    #pragma unroll
    for (int i = 0; i < 16; i++) acc[i] = 0ull;

    // double-buffered gather: one LDG.128 in flight ahead
    ulonglong2 A = *(const ulonglong2*)(fb + (size_t)sidx[wid][0] * C_);

    #pragma unroll 4
    for (int k = 0; k < K_; k++) {
        ulonglong2 cur = A;
        if (k + 1 < K_)
            A = *(const ulonglong2*)(fb + (size_t)sidx[wid][k + 1] * C_);

        const float g = sgd[wid][k * H_ + hd];   // scalar broadcast LDS
        unsigned long long gg, s0, s1;
        asm("mov.b64 %0, {%1, %1};" : "=l"(gg) : "f"(g));
        asm("mul.rn.f32x2 %0, %1, %2;" : "=l"(s0) : "l"(cur.x), "l"(gg)); // ch {4cq,4cq+1}
        asm("mul.rn.f32x2 %0, %1, %2;" : "=l"(s1) : "l"(cur.y), "l"(gg)); // ch {4cq+2,4cq+3}

        // this lane's 8 W values: 2 uniform LDS.128
        const float4* wr = (const float4*)(swn[wid] + k * CMID_ + 8 * wh);
        float4 Wa = wr[0];
        float4 Wb = wr[1];
        unsigned long long w0, w1, w2, w3, w4, w5, w6, w7;
        asm("mov.b64 %0, {%1, %1};" : "=l"(w0) : "f"(Wa.x));
        asm("mov.b64 %0, {%1, %1};" : "=l"(w1) : "f"(Wa.y));
        asm("mov.b64 %0, {%1, %1};" : "=l"(w2) : "f"(Wa.z));
        asm("mov.b64 %0, {%1, %1};" : "=l"(w3) : "f"(Wa.w));
        asm("mov.b64 %0, {%1, %1};" : "=l"(w4) : "f"(Wb.x));
        asm("mov.b64 %0, {%1, %1};" : "=l"(w5) : "f"(Wb.y));
        asm("mov.b64 %0, {%1, %1};" : "=l"(w6) : "f"(Wb.z));
        asm("mov.b64 %0, {%1, %1};" : "=l"(w7) : "f"(Wb.w));

        asm("fma.rn.f32x2 %0, %1, %2, %3;" : "=l"(acc[ 0]) : "l"(s0), "l"(w0), "l"(acc[ 0]));
        asm("fma.rn.f32x2 %0, %1, %2, %3;" : "=l"(acc[ 1]) : "l"(s0), "l"(w1), "l"(acc[ 1]));
        asm("fma.rn.f32x2 %0, %1, %2, %3;" : "=l"(acc[ 2]) : "l"(s0), "l"(w2), "l"(acc[ 2]));
        asm("fma.rn.f32x2 %0, %1, %2, %3;" : "=l"(acc[ 3]) : "l"(s0), "l"(w3), "l"(acc[ 3]));
        asm("fma.rn.f32x2 %0, %1, %2, %3;" : "=l"(acc[ 4]) : "l"(s0), "l"(w4), "l"(acc[ 4]));
        asm("fma.rn.f32x2 %0, %1, %2, %3;" : "=l"(acc[ 5]) : "l"(s0), "l"(w5), "l"(acc[ 5]));
        asm("fma.rn.f32x2 %0, %1, %2, %3;" : "=l"(acc[ 6]) : "l"(s0), "l"(w6), "l"(acc[ 6]));
        asm("fma.rn.f32x2 %0, %1, %2, %3;" : "=l"(acc[ 7]) : "l"(s0), "l"(w7), "l"(acc[ 7]));
        asm("fma.rn.f32x2 %0, %1, %2, %3;" : "=l"(acc[ 8]) : "l"(s1), "l"(w0), "l"(acc[ 8]));
        asm("fma.rn.f32x2 %0, %1, %2, %3;" : "=l"(acc[ 9]) : "l"(s1), "l"(w1), "l"(acc[ 9]));
        asm("fma.rn.f32x2 %0, %1, %2, %3;" : "=l"(acc[10]) : "l"(s1), "l"(w2), "l"(acc[10]));
        asm("fma.rn.f32x2 %0, %1, %2, %3;" : "=l"(acc[11]) : "l"(s1), "l"(w3), "l"(acc[11]));
        asm("fma.rn.f32x2 %0, %1, %2, %3;" : "=l"(acc[12]) : "l"(s1), "l"(w4), "l"(acc[12]));
        asm("fma.rn.f32x2 %0, %1, %2, %3;" : "=l"(acc[13]) : "l"(s1), "l"(w5), "l"(acc[13]));
        asm("fma.rn.f32x2 %0, %1, %2, %3;" : "=l"(acc[14]) : "l"(s1), "l"(w6), "l"(acc[14]));
        asm("fma.rn.f32x2 %0, %1, %2, %3;" : "=l"(acc[15]) : "l"(s1), "l"(w7), "l"(acc[15]));
    }

    // ---- epilogue: rows 4cq+2i (lo halves) and 4cq+2i+1 (hi halves), w 8wh..+8
    float* o = out + (size_t)p * (C_ * CMID_) + (size_t)(4 * cq) * CMID_ + 8 * wh;
    #pragma unroll
    for (int i = 0; i < 2; i++) {
        const unsigned long long* a = acc + i * 8;
        float2 v0 = *(float2*)&a[0], v1 = *(float2*)&a[1];
        float2 v2 = *(float2*)&a[2], v3 = *(float2*)&a[3];
        float2 v4 = *(float2*)&a[4], v5 = *(float2*)&a[5];
        float2 v6 = *(float2*)&a[6], v7 = *(float2*)&a[7];
        float* r0 = o + (2 * i) * CMID_;
        float* r1 = o + (2 * i + 1) * CMID_;
        *(float4*)(r0)     = make_float4(v0.x, v1.x, v2.x, v3.x);
        *(float4*)(r0 + 4) = make_float4(v4.x, v5.x, v6.x, v7.x);
        *(float4*)(r1)     = make_float4(v0.y, v1.y, v2.y, v3.y);
        *(float4*)(r1 + 4) = make_float4(v4.y, v5.y, v6.y, v7.y);
    }
}

extern "C" void kernel_launch(void* const* d_in, const int* in_sizes, int n_in,
                              void* d_out, int out_size) {
    const float* feat = (const float*)d_in[0];
    const void*  inds = d_in[1];
    const float* guid = (const float*)d_in[2];
    const float* wn   = (const float*)d_in[3];
    float* out = (float*)d_out;

    detect_idx_kernel<<<1, 32>>>((const unsigned int*)inds);
    pcf_kernel<<<(B_ * M_) / 4, 128>>>(feat, inds, guid, wn, out);
}